// round 4
// baseline (speedup 1.0000x reference)
#include <cuda_runtime.h>
#include <cuda_bf16.h>

typedef unsigned long long ull;

#define NB 2
#define NPB 4096
#define NTOT (NB*NPB)
#define ULLMAX 0xFFFFFFFFFFFFFFFFull

// ---------------- scratch ----------------
__device__ float g_y[NTOT*64];
__device__ float g_sq[NTOT];
__device__ int   g_nbr[NTOT*7];
__device__ float g_h0[NTOT*64], g_h1[NTOT*64];
__device__ float g_f10[NTOT], g_f20[NTOT], g_f11[NTOT], g_f21[NTOT];
__device__ float g_hcat[NTOT*128];
__device__ float g_ho[NTOT*64];
__device__ float g_f1o[NTOT], g_f2o[NTOT];
__device__ float g_outn[NTOT*64];
__device__ float g_wt[9*64*64];      // convT weights [k][ci][co]
__device__ float g_wc[31*9*64];      // conv-head weights [ci*9+k][co]
__device__ float g_va[4*64];         // folded attention vecs heads 0/1
__device__ float g_vaO[2*128];       // folded attention vecs out head

__device__ __forceinline__ ull fma2(ull a, ull b, ull c) {
    ull d;
    asm("fma.rn.f32x2 %0, %1, %2, %3;" : "=l"(d) : "l"(a), "l"(b), "l"(c));
    return d;
}

// ---------------- K0: prep (repacks + folded attention vectors) ----------------
__global__ void prep_kernel(const float* __restrict__ w_last,
                            const float* __restrict__ w_head,
                            const float* __restrict__ W0, const float* __restrict__ a0,
                            const float* __restrict__ W1, const float* __restrict__ a1,
                            const float* __restrict__ W_out, const float* __restrict__ a_out) {
    int idx = blockIdx.x * 256 + threadIdx.x;
    if (idx < 36864) {
        int co = idx & 63, ci = (idx >> 6) & 63, k = idx >> 12;
        g_wt[(k*64 + ci)*64 + co] = w_last[(ci*64 + co)*9 + k];
    } else if (idx < 36864 + 17856) {
        int j = idx - 36864;          // j = (ci*9+k)*64+co
        int co = j & 63, rest = j >> 6;
        int k = rest % 9, ci = rest / 9;
        g_wc[j] = w_head[(co*31 + ci)*9 + k];
    } else if (idx < 36864 + 17856 + 256) {
        int j = idx - 54720;
        int head = j >> 7, which = (j >> 6) & 1, k = j & 63;
        const float* W = head ? W1 : W0;
        const float* a = head ? a1 : a0;
        float s = 0.f;
        for (int c = 0; c < 64; c++) s += W[k*64 + c] * a[which*64 + c];
        g_va[(head*2 + which)*64 + k] = s;
    } else if (idx < 36864 + 17856 + 512) {
        int j = idx - 54976;
        int which = j >> 7, k = j & 127;
        float s = 0.f;
        for (int c = 0; c < 64; c++) s += W_out[k*64 + c] * a_out[which*64 + c];
        g_vaO[which*128 + k] = s;
    }
}

// ---------------- K1: conv head (k3 s2 p1), register tiled ----------------
__global__ void conv_head_kernel(const float* __restrict__ x,
                                 const float* __restrict__ bias) {
    int b = blockIdx.x >> 6;
    int oh = blockIdx.x & 63;
    __shared__ float sIn[31*3*130];   // [ci][kh][iwp], iwp = iw+1
    int t = threadIdx.x;              // 256
    for (int idx = t; idx < 31*3*130; idx += 256) {
        int iwp = idx % 130;
        int rem = idx / 130;
        int r = rem % 3, ci = rem / 3;
        int ih = oh*2 - 1 + r, iw = iwp - 1;
        float v = 0.f;
        if ((unsigned)ih < 128u && (unsigned)iw < 128u)
            v = x[((b*31 + ci)*128 + ih)*128 + iw];
        sIn[idx] = v;
    }
    __syncthreads();
    int cog = t & 15, owg = t >> 4;   // co = cog*4+cc, ow = owg*4+q
    float acc[4][4];
    #pragma unroll
    for (int q = 0; q < 4; q++)
        #pragma unroll
        for (int cc = 0; cc < 4; cc++) acc[q][cc] = 0.f;
    for (int ci = 0; ci < 31; ci++) {
        #pragma unroll
        for (int r = 0; r < 3; r++) {
            int ib = (ci*3 + r)*130 + owg*8;
            #pragma unroll
            for (int kw = 0; kw < 3; kw++) {
                float4 wv = *(const float4*)&g_wc[((ci*9 + r*3 + kw)*64) + cog*4];
                #pragma unroll
                for (int q = 0; q < 4; q++) {
                    float iv = sIn[ib + 2*q + kw];
                    acc[q][0] += iv * wv.x;
                    acc[q][1] += iv * wv.y;
                    acc[q][2] += iv * wv.z;
                    acc[q][3] += iv * wv.w;
                }
            }
        }
    }
    float4 bv = *(const float4*)&bias[cog*4];
    #pragma unroll
    for (int q = 0; q < 4; q++) {
        int node = b*4096 + oh*64 + owg*4 + q;
        float4 o;
        o.x = acc[q][0] + bv.x; o.y = acc[q][1] + bv.y;
        o.z = acc[q][2] + bv.z; o.w = acc[q][3] + bv.w;
        *(float4*)&g_y[node*64 + cog*4] = o;
    }
}

// ---------------- K2: squared norms ----------------
__global__ void sq_kernel() {
    int node = blockIdx.x*8 + (threadIdx.x >> 5);
    int lane = threadIdx.x & 31;
    const float* p = &g_y[node*64];
    float a = p[lane], b = p[lane + 32];
    float v = a*a + b*b;
    #pragma unroll
    for (int off = 16; off; off >>= 1) v += __shfl_down_sync(0xffffffffu, v, off);
    if (lane == 0) g_sq[node] = v;
}

// ---------------- K3: fused Gram + top-7 kNN (f32x2 packed FFMA) ----------------
#define TI 32
#define TJ 128
__global__ void __launch_bounds__(256, 1) knn_kernel() {
    __shared__ __align__(16) float yi[TI*68];
    __shared__ __align__(16) float yj[TJ*68];
    __shared__ float sqi[TI];
    __shared__ float sqj[TJ];
    int t = threadIdx.x;
    int i0 = blockIdx.x * TI;
    int base = i0 & ~4095;
    int ig = t >> 5, jg = t & 31;     // warp = one ig; 4 i-rows = ig*4+ii ; j-cols = jg+32m

    for (int idx = t; idx < TI*16; idx += 256) {
        int row = idx >> 4, c4 = idx & 15;
        *(float4*)&yi[row*68 + c4*4] = *(const float4*)&g_y[(i0 + row)*64 + c4*4];
    }
    if (t < TI) sqi[t] = g_sq[i0 + t];
    __syncthreads();
    float sqir[4];
    #pragma unroll
    for (int ii = 0; ii < 4; ii++) sqir[ii] = sqi[ig*4 + ii];

    float bd[4][7]; int bj[4][7];
    #pragma unroll
    for (int ii = 0; ii < 4; ii++)
        #pragma unroll
        for (int s = 0; s < 7; s++) { bd[ii][s] = 3.4e38f; bj[ii][s] = 0x7fffffff; }

    for (int jt = 0; jt < NPB; jt += TJ) {
        __syncthreads();
        for (int idx = t; idx < TJ*16; idx += 256) {
            int row = idx >> 4, c4 = idx & 15;
            *(float4*)&yj[row*68 + c4*4] = *(const float4*)&g_y[(base + jt + row)*64 + c4*4];
        }
        if (t < TJ) sqj[t] = g_sq[base + jt + t];
        __syncthreads();

        ull acc2[4][4];
        #pragma unroll
        for (int ii = 0; ii < 4; ii++)
            #pragma unroll
            for (int m = 0; m < 4; m++) acc2[ii][m] = 0ull;

        #pragma unroll
        for (int c = 0; c < 64; c += 4) {
            ulonglong2 av[4], bv[4];
            #pragma unroll
            for (int ii = 0; ii < 4; ii++)
                av[ii] = *(const ulonglong2*)&yi[(ig*4 + ii)*68 + c];
            #pragma unroll
            for (int m = 0; m < 4; m++)
                bv[m] = *(const ulonglong2*)&yj[(jg + 32*m)*68 + c];
            #pragma unroll
            for (int ii = 0; ii < 4; ii++)
                #pragma unroll
                for (int m = 0; m < 4; m++) {
                    acc2[ii][m] = fma2(av[ii].x, bv[m].x, acc2[ii][m]);
                    acc2[ii][m] = fma2(av[ii].y, bv[m].y, acc2[ii][m]);
                }
        }

        float sqjv[4];
        #pragma unroll
        for (int m = 0; m < 4; m++) sqjv[m] = sqj[jg + 32*m];
        #pragma unroll
        for (int ii = 0; ii < 4; ii++) {
            float si = sqir[ii];
            #pragma unroll
            for (int m = 0; m < 4; m++) {
                float lo = __uint_as_float((unsigned)(acc2[ii][m] & 0xffffffffull));
                float hi = __uint_as_float((unsigned)(acc2[ii][m] >> 32));
                float dot = lo + hi;
                float d2 = si + sqjv[m] - 2.f*dot;
                d2 = fmaxf(d2, 0.f);
                // ascending-j scan + strict-less keeps smallest-j on ties (stable)
                if (d2 < bd[ii][6]) {
                    int j = jt + jg + 32*m;
                    bd[ii][6] = d2; bj[ii][6] = j;
                    #pragma unroll
                    for (int s = 5; s >= 0; s--) {
                        if (bd[ii][s+1] < bd[ii][s]) {
                            float td = bd[ii][s]; bd[ii][s] = bd[ii][s+1]; bd[ii][s+1] = td;
                            int tj = bj[ii][s]; bj[ii][s] = bj[ii][s+1]; bj[ii][s+1] = tj;
                        }
                    }
                }
            }
        }
    }

    // merge 32 sorted 7-lists per row via warp reduction (64-bit keys, unique j)
    ull* keys = (ull*)yj;             // 256*7 ull = 14336B, overlays yj
    int lane = jg;
    for (int ii = 0; ii < 4; ii++) {
        __syncthreads();
        #pragma unroll
        for (int s = 0; s < 7; s++)
            keys[t*7 + s] = ((ull)__float_as_uint(bd[ii][s]) << 32) | (unsigned)bj[ii][s];
        __syncthreads();
        int r = ig*4 + ii;
        ull mine[7];
        #pragma unroll
        for (int s = 0; s < 7; s++) mine[s] = keys[(ig*32 + lane)*7 + s];
        #pragma unroll
        for (int s = 0; s < 7; s++) {
            ull cur = mine[0];
            ull m = cur;
            #pragma unroll
            for (int off = 16; off; off >>= 1) {
                ull o = __shfl_down_sync(0xffffffffu, m, off);
                if (o < m) m = o;
            }
            m = __shfl_sync(0xffffffffu, m, 0);
            if (cur == m) {
                mine[0]=mine[1]; mine[1]=mine[2]; mine[2]=mine[3];
                mine[3]=mine[4]; mine[4]=mine[5]; mine[5]=mine[6]; mine[6]=ULLMAX;
            }
            if (lane == 0) g_nbr[(i0 + r)*7 + s] = (int)(unsigned)(m & 0xffffffffu);
        }
    }
}

// ---------------- K4: proj heads 0/1 (tiled GEMM, f-scalars folded) ----------------
__global__ void proj01_kernel(const float* __restrict__ W0,
                              const float* __restrict__ W1) {
    __shared__ float ys[32*68];
    __shared__ float Wc[64*136];
    int t = threadIdx.x;
    int i0 = blockIdx.x * 32;
    for (int idx = t; idx < 64*136; idx += 256) {
        int k = idx / 136, c = idx % 136;
        float v = 0.f;
        if (c < 64) v = W0[k*64 + c];
        else if (c < 128) v = W1[k*64 + c - 64];
        else if (c < 132) v = g_va[(c - 128)*64 + k];
        Wc[idx] = v;
    }
    for (int idx = t; idx < 2048; idx += 256) {
        int n = idx >> 6, k = idx & 63;
        ys[n*68 + k] = g_y[(i0 + n)*64 + k];
    }
    __syncthreads();
    int cg = t & 31, ng = t >> 5;     // 4 nodes, cols cg+32m (m<4) and 128+cg (cg<4)
    float acc[4][5];
    #pragma unroll
    for (int nn = 0; nn < 4; nn++)
        #pragma unroll
        for (int m = 0; m < 5; m++) acc[nn][m] = 0.f;
    for (int k = 0; k < 64; k++) {
        float w0 = Wc[k*136 + cg];
        float w1 = Wc[k*136 + cg + 32];
        float w2 = Wc[k*136 + cg + 64];
        float w3 = Wc[k*136 + cg + 96];
        float w4 = (cg < 4) ? Wc[k*136 + 128 + cg] : 0.f;
        #pragma unroll
        for (int nn = 0; nn < 4; nn++) {
            float yv = ys[(ng*4 + nn)*68 + k];
            acc[nn][0] += yv*w0; acc[nn][1] += yv*w1;
            acc[nn][2] += yv*w2; acc[nn][3] += yv*w3;
            acc[nn][4] += yv*w4;
        }
    }
    #pragma unroll
    for (int nn = 0; nn < 4; nn++) {
        int node = i0 + ng*4 + nn;
        g_h0[node*64 + cg]      = acc[nn][0];
        g_h0[node*64 + cg + 32] = acc[nn][1];
        g_h1[node*64 + cg]      = acc[nn][2];
        g_h1[node*64 + cg + 32] = acc[nn][3];
        if (cg == 0) g_f10[node] = acc[nn][4];
        else if (cg == 1) g_f20[node] = acc[nn][4];
        else if (cg == 2) g_f11[node] = acc[nn][4];
        else if (cg == 3) g_f21[node] = acc[nn][4];
    }
}

// ---------------- K5: sparse attention agg heads 0/1 + relu ----------------
__global__ void agg01_kernel() {
    int t = threadIdx.x;
    int node = blockIdx.x*2 + (t >> 7);
    int head = (t >> 6) & 1, c = t & 63;
    int bb = node & ~4095;
    int nb[7];
    #pragma unroll
    for (int s = 0; s < 7; s++) nb[s] = bb + g_nbr[node*7 + s];
    const float* f1 = head ? g_f11 : g_f10;
    const float* f2 = head ? g_f21 : g_f20;
    const float* h  = head ? g_h1  : g_h0;
    float fi = f1[node];
    float e[7], m = -3.4e38f;
    #pragma unroll
    for (int s = 0; s < 7; s++) {
        float v = fi + f2[nb[s]];
        v = v > 0.f ? v : 0.2f*v;
        e[s] = v; if (v > m) m = v;
    }
    float sum = 0.f;
    #pragma unroll
    for (int s = 0; s < 7; s++) { e[s] = expf(e[s] - m); sum += e[s]; }
    float inv = 1.f / sum;
    float acc = 0.f;
    #pragma unroll
    for (int s = 0; s < 7; s++) acc += e[s]*inv * h[nb[s]*64 + c];
    acc = acc > 0.f ? acc : 0.f;
    g_hcat[node*128 + head*64 + c] = acc;
}

// ---------------- K6: out-head projection (tiled GEMM, f folded) ----------------
__global__ void projout_kernel(const float* __restrict__ W_out) {
    __shared__ float hs[16*136];
    __shared__ float Wo[128*72];
    int t = threadIdx.x;
    int i0 = blockIdx.x * 16;
    for (int idx = t; idx < 128*72; idx += 256) {
        int k = idx / 72, c = idx % 72;
        float v = 0.f;
        if (c < 64) v = W_out[k*64 + c];
        else if (c == 64) v = g_vaO[k];
        else if (c == 65) v = g_vaO[128 + k];
        Wo[idx] = v;
    }
    for (int idx = t; idx < 2048; idx += 256) {
        int n = idx >> 7, k = idx & 127;
        hs[n*136 + k] = g_hcat[(i0 + n)*128 + k];
    }
    __syncthreads();
    int cg = t & 31, ng = t >> 5;     // 2 nodes, cols cg, cg+32, and 64+cg (cg<2)
    float acc[2][3];
    #pragma unroll
    for (int nn = 0; nn < 2; nn++)
        #pragma unroll
        for (int m = 0; m < 3; m++) acc[nn][m] = 0.f;
    for (int k = 0; k < 128; k++) {
        float w0 = Wo[k*72 + cg];
        float w1 = Wo[k*72 + cg + 32];
        float w2 = (cg < 2) ? Wo[k*72 + 64 + cg] : 0.f;
        #pragma unroll
        for (int nn = 0; nn < 2; nn++) {
            float yv = hs[(ng*2 + nn)*136 + k];
            acc[nn][0] += yv*w0; acc[nn][1] += yv*w1; acc[nn][2] += yv*w2;
        }
    }
    #pragma unroll
    for (int nn = 0; nn < 2; nn++) {
        int node = i0 + ng*2 + nn;
        g_ho[node*64 + cg]      = acc[nn][0];
        g_ho[node*64 + cg + 32] = acc[nn][1];
        if (cg == 0) g_f1o[node] = acc[nn][2];
        else if (cg == 1) g_f2o[node] = acc[nn][2];
    }
}

// ---------------- K7: out-head agg + elu + log_softmax ----------------
__global__ void aggout_kernel() {
    __shared__ float wmax[4][2];
    __shared__ float wsum[4][2];
    int t = threadIdx.x;
    int ln = t >> 6, c = t & 63;
    int node = blockIdx.x*4 + ln;
    int lane = t & 31, wh = (t >> 5) & 1;
    int bb = node & ~4095;
    int nb[7];
    #pragma unroll
    for (int s = 0; s < 7; s++) nb[s] = bb + g_nbr[node*7 + s];
    float fi = g_f1o[node];
    float e[7], m = -3.4e38f;
    #pragma unroll
    for (int s = 0; s < 7; s++) {
        float v = fi + g_f2o[nb[s]];
        v = v > 0.f ? v : 0.2f*v;
        e[s] = v; if (v > m) m = v;
    }
    float sum = 0.f;
    #pragma unroll
    for (int s = 0; s < 7; s++) { e[s] = expf(e[s] - m); sum += e[s]; }
    float inv = 1.f / sum;
    float acc = 0.f;
    #pragma unroll
    for (int s = 0; s < 7; s++) acc += e[s]*inv * g_ho[nb[s]*64 + c];
    float v = acc > 0.f ? acc : (expf(acc) - 1.f);

    float mx = v;
    #pragma unroll
    for (int off = 16; off; off >>= 1) mx = fmaxf(mx, __shfl_down_sync(0xffffffffu, mx, off));
    if (lane == 0) wmax[ln][wh] = mx;
    __syncthreads();
    mx = fmaxf(wmax[ln][0], wmax[ln][1]);
    float p = expf(v - mx);
    float ssum = p;
    #pragma unroll
    for (int off = 16; off; off >>= 1) ssum += __shfl_down_sync(0xffffffffu, ssum, off);
    if (lane == 0) wsum[ln][wh] = ssum;
    __syncthreads();
    float tot = wsum[ln][0] + wsum[ln][1];
    g_outn[node*64 + c] = v - mx - logf(tot);
}

// ---------------- K8: ConvTranspose2d (register tiled) ----------------
__global__ void convt_kernel(const float* __restrict__ b_last, float* __restrict__ out) {
    int b = blockIdx.x >> 7;
    int oh = blockIdx.x & 127;
    __shared__ __align__(16) float sin[2][64*68];
    int khs[2], ihs[2];
    int cnt = 0;
    for (int kh = 0; kh < 3; kh++) {
        int num = oh + 1 - kh;
        if (num & 1) continue;
        int ih = num >> 1;
        if (ih < 0 || ih >= 64) continue;
        khs[cnt] = kh; ihs[cnt] = ih; cnt++;
    }
    int t = threadIdx.x;
    for (int r = 0; r < cnt; r++) {
        const float* src = &g_outn[((b << 12) + ihs[r]*64)*64];
        for (int idx = t; idx < 1024; idx += 256) {
            int iw = idx >> 4, c4 = idx & 15;
            *(float4*)&sin[r][iw*68 + c4*4] = *(const float4*)&src[iw*64 + c4*4];
        }
    }
    __syncthreads();
    int cog = t & 15, owg = t >> 4;   // co = cog*4+cc, ow = owg*8+q
    float acc[8][4];
    #pragma unroll
    for (int q = 0; q < 8; q++)
        #pragma unroll
        for (int cc = 0; cc < 4; cc++) acc[q][cc] = 0.f;

    for (int r = 0; r < cnt; r++) {
        int kh = khs[r];
        #pragma unroll
        for (int kw = 0; kw < 3; kw++) {
            int iwq[4]; bool vq[4];
            #pragma unroll
            for (int u = 0; u < 4; u++) {
                int q = ((kw + 1) & 1) + 2*u;
                int num = owg*8 + q + 1 - kw;
                int iw = num >> 1;
                iwq[u] = iw;
                vq[u] = (num >= 0) && (iw < 64);
            }
            const float* wbase = &g_wt[(kh*3 + kw)*4096 + cog*4];
            for (int ci0 = 0; ci0 < 64; ci0 += 4) {
                float4 w0 = *(const float4*)&wbase[(ci0+0)*64];
                float4 w1 = *(const float4*)&wbase[(ci0+1)*64];
                float4 w2 = *(const float4*)&wbase[(ci0+2)*64];
                float4 w3 = *(const float4*)&wbase[(ci0+3)*64];
                #pragma unroll
                for (int u = 0; u < 4; u++) {
                    if (!vq[u]) continue;
                    int q = ((kw + 1) & 1) + 2*u;
                    float4 iv = *(const float4*)&sin[r][iwq[u]*68 + ci0];
                    #pragma unroll
                    for (int cc = 0; cc < 4; cc++) {
                        float wv0 = (&w0.x)[cc], wv1 = (&w1.x)[cc],
                              wv2 = (&w2.x)[cc], wv3 = (&w3.x)[cc];
                        acc[q][cc] += iv.x*wv0 + iv.y*wv1 + iv.z*wv2 + iv.w*wv3;
                    }
                }
            }
        }
    }
    #pragma unroll
    for (int cc = 0; cc < 4; cc++) {
        int co = cog*4 + cc;
        float bv = b_last[co];
        float4 o0, o1;
        o0.x = acc[0][cc]+bv; o0.y = acc[1][cc]+bv; o0.z = acc[2][cc]+bv; o0.w = acc[3][cc]+bv;
        o1.x = acc[4][cc]+bv; o1.y = acc[5][cc]+bv; o1.z = acc[6][cc]+bv; o1.w = acc[7][cc]+bv;
        float* dst = &out[((b*64 + co)*128 + oh)*128 + owg*8];
        *(float4*)&dst[0] = o0;
        *(float4*)&dst[4] = o1;
    }
}

// ---------------- launcher ----------------
extern "C" void kernel_launch(void* const* d_in, const int* in_sizes, int n_in,
                              void* d_out, int out_size) {
    const float* x      = (const float*)d_in[0];
    const float* w_head = (const float*)d_in[1];
    const float* b_head = (const float*)d_in[2];
    const float* W0     = (const float*)d_in[3];
    const float* a0     = (const float*)d_in[4];
    const float* W1     = (const float*)d_in[5];
    const float* a1     = (const float*)d_in[6];
    const float* W_out  = (const float*)d_in[7];
    const float* a_out  = (const float*)d_in[8];
    const float* w_last = (const float*)d_in[9];
    const float* b_last = (const float*)d_in[10];
    float* out = (float*)d_out;

    prep_kernel<<<216, 256>>>(w_last, w_head, W0, a0, W1, a1, W_out, a_out);
    conv_head_kernel<<<128, 256>>>(x, b_head);
    sq_kernel<<<1024, 256>>>();
    knn_kernel<<<NTOT/TI, 256>>>();
    proj01_kernel<<<NTOT/32, 256>>>(W0, W1);
    agg01_kernel<<<NTOT/2, 256>>>();
    projout_kernel<<<NTOT/16, 256>>>(W_out);
    aggout_kernel<<<NTOT/4, 256>>>();
    convt_kernel<<<NB*128, 256>>>(b_last, out);
}

// round 5
// speedup vs baseline: 1.0312x; 1.0312x over previous
#include <cuda_runtime.h>
#include <cuda_bf16.h>

typedef unsigned long long ull;

#define NB 2
#define NPB 4096
#define NTOT (NB*NPB)

// ---------------- scratch ----------------
__device__ float g_y[NTOT*64];
__device__ float g_sq[NTOT];
__device__ int   g_nbr[NTOT*7];
__device__ float g_h0[NTOT*64], g_h1[NTOT*64];
__device__ float g_f10[NTOT], g_f20[NTOT], g_f11[NTOT], g_f21[NTOT];
__device__ float g_hcat[NTOT*128];
__device__ float g_ho[NTOT*64];
__device__ float g_f1o[NTOT], g_f2o[NTOT];
__device__ float g_outn[NTOT*64];
__device__ float g_wt[9*64*64];      // convT weights [k][ci][co]
__device__ float g_wc[31*9*64];      // conv-head weights [ci*9+k][co]
__device__ float g_va[4*64];         // folded attention vecs heads 0/1
__device__ float g_vaO[2*128];       // folded attention vecs out head

__device__ __forceinline__ ull fma2(ull a, ull b, ull c) {
    ull d;
    asm("fma.rn.f32x2 %0, %1, %2, %3;" : "=l"(d) : "l"(a), "l"(b), "l"(c));
    return d;
}

// ---------------- K0: prep (repacks + folded attention vectors) ----------------
__global__ void prep_kernel(const float* __restrict__ w_last,
                            const float* __restrict__ w_head,
                            const float* __restrict__ W0, const float* __restrict__ a0,
                            const float* __restrict__ W1, const float* __restrict__ a1,
                            const float* __restrict__ W_out, const float* __restrict__ a_out) {
    int idx = blockIdx.x * 256 + threadIdx.x;
    if (idx < 36864) {
        int co = idx & 63, ci = (idx >> 6) & 63, k = idx >> 12;
        g_wt[(k*64 + ci)*64 + co] = w_last[(ci*64 + co)*9 + k];
    } else if (idx < 36864 + 17856) {
        int j = idx - 36864;          // j = (ci*9+k)*64+co
        int co = j & 63, rest = j >> 6;
        int k = rest % 9, ci = rest / 9;
        g_wc[j] = w_head[(co*31 + ci)*9 + k];
    } else if (idx < 36864 + 17856 + 256) {
        int j = idx - 54720;
        int head = j >> 7, which = (j >> 6) & 1, k = j & 63;
        const float* W = head ? W1 : W0;
        const float* a = head ? a1 : a0;
        float s = 0.f;
        for (int c = 0; c < 64; c++) s += W[k*64 + c] * a[which*64 + c];
        g_va[(head*2 + which)*64 + k] = s;
    } else if (idx < 36864 + 17856 + 512) {
        int j = idx - 54976;
        int which = j >> 7, k = j & 127;
        float s = 0.f;
        for (int c = 0; c < 64; c++) s += W_out[k*64 + c] * a_out[which*64 + c];
        g_vaO[which*128 + k] = s;
    }
}

// ---------------- K1: conv head (k3 s2 p1) + fused squared norms ----------------
__global__ void conv_head_kernel(const float* __restrict__ x,
                                 const float* __restrict__ bias) {
    int b = blockIdx.x >> 6;
    int oh = blockIdx.x & 63;
    __shared__ float sIn[31*3*130];   // [ci][kh][iwp], iwp = iw+1
    int t = threadIdx.x;              // 256
    for (int idx = t; idx < 31*3*130; idx += 256) {
        int iwp = idx % 130;
        int rem = idx / 130;
        int r = rem % 3, ci = rem / 3;
        int ih = oh*2 - 1 + r, iw = iwp - 1;
        float v = 0.f;
        if ((unsigned)ih < 128u && (unsigned)iw < 128u)
            v = x[((b*31 + ci)*128 + ih)*128 + iw];
        sIn[idx] = v;
    }
    __syncthreads();
    int cog = t & 15, owg = t >> 4;   // co = cog*4+cc, ow = owg*4+q
    float acc[4][4];
    #pragma unroll
    for (int q = 0; q < 4; q++)
        #pragma unroll
        for (int cc = 0; cc < 4; cc++) acc[q][cc] = 0.f;
    for (int ci = 0; ci < 31; ci++) {
        #pragma unroll
        for (int r = 0; r < 3; r++) {
            int ib = (ci*3 + r)*130 + owg*8;
            #pragma unroll
            for (int kw = 0; kw < 3; kw++) {
                float4 wv = *(const float4*)&g_wc[((ci*9 + r*3 + kw)*64) + cog*4];
                #pragma unroll
                for (int q = 0; q < 4; q++) {
                    float iv = sIn[ib + 2*q + kw];
                    acc[q][0] += iv * wv.x;
                    acc[q][1] += iv * wv.y;
                    acc[q][2] += iv * wv.z;
                    acc[q][3] += iv * wv.w;
                }
            }
        }
    }
    float4 bv = *(const float4*)&bias[cog*4];
    float ssq[4];
    #pragma unroll
    for (int q = 0; q < 4; q++) {
        int node = b*4096 + oh*64 + owg*4 + q;
        float4 o;
        o.x = acc[q][0] + bv.x; o.y = acc[q][1] + bv.y;
        o.z = acc[q][2] + bv.z; o.w = acc[q][3] + bv.w;
        *(float4*)&g_y[node*64 + cog*4] = o;
        ssq[q] = o.x*o.x + o.y*o.y + o.z*o.z + o.w*o.w;
    }
    // reduce ssq over the 16 cog-lanes (same owg = same half-warp group)
    #pragma unroll
    for (int off = 1; off <= 8; off <<= 1)
        #pragma unroll
        for (int q = 0; q < 4; q++)
            ssq[q] += __shfl_xor_sync(0xffffffffu, ssq[q], off);
    if (cog == 0) {
        #pragma unroll
        for (int q = 0; q < 4; q++)
            g_sq[b*4096 + oh*64 + owg*4 + q] = ssq[q];
    }
}

// ---------------- K3: fused Gram + top-7 kNN (f32x2, 4x2 tile, 2 CTA/SM) ----------------
#define TI 32
#define TJ 64
__global__ void __launch_bounds__(256, 2) knn_kernel() {
    __shared__ __align__(16) float yi[TI*68];
    __shared__ __align__(16) float yj[TJ*68];
    __shared__ float sqi[TI];
    __shared__ float sqj[TJ];
    int t = threadIdx.x;
    int i0 = blockIdx.x * TI;
    int base = i0 & ~4095;
    int ig = t >> 5, jg = t & 31;     // warp = one ig; 4 i-rows = ig*4+ii ; j-cols = jg+32m (m<2)

    for (int idx = t; idx < TI*16; idx += 256) {
        int row = idx >> 4, c4 = idx & 15;
        *(float4*)&yi[row*68 + c4*4] = *(const float4*)&g_y[(i0 + row)*64 + c4*4];
    }
    if (t < TI) sqi[t] = g_sq[i0 + t];
    __syncthreads();
    float sqir[4];
    #pragma unroll
    for (int ii = 0; ii < 4; ii++) sqir[ii] = sqi[ig*4 + ii];

    const ull SENT = ((ull)0x7F7FFFFFull << 32) | 0x7FFFFFFFull;  // (FLT_MAX, INT_MAX)
    ull ktop[4][7];
    float bd6[4];
    #pragma unroll
    for (int ii = 0; ii < 4; ii++) {
        #pragma unroll
        for (int s = 0; s < 7; s++) ktop[ii][s] = SENT;
        bd6[ii] = 3.4028235e38f;
    }

    for (int jt = 0; jt < NPB; jt += TJ) {
        __syncthreads();
        for (int idx = t; idx < TJ*16; idx += 256) {
            int row = idx >> 4, c4 = idx & 15;
            *(float4*)&yj[row*68 + c4*4] = *(const float4*)&g_y[(base + jt + row)*64 + c4*4];
        }
        if (t < TJ) sqj[t] = g_sq[base + jt + t];
        __syncthreads();

        ull acc2[4][2];
        #pragma unroll
        for (int ii = 0; ii < 4; ii++) { acc2[ii][0] = 0ull; acc2[ii][1] = 0ull; }

        #pragma unroll
        for (int c = 0; c < 64; c += 4) {
            ulonglong2 av[4], bv[2];
            #pragma unroll
            for (int ii = 0; ii < 4; ii++)
                av[ii] = *(const ulonglong2*)&yi[(ig*4 + ii)*68 + c];
            #pragma unroll
            for (int m = 0; m < 2; m++)
                bv[m] = *(const ulonglong2*)&yj[(jg + 32*m)*68 + c];
            #pragma unroll
            for (int ii = 0; ii < 4; ii++)
                #pragma unroll
                for (int m = 0; m < 2; m++) {
                    acc2[ii][m] = fma2(av[ii].x, bv[m].x, acc2[ii][m]);
                    acc2[ii][m] = fma2(av[ii].y, bv[m].y, acc2[ii][m]);
                }
        }

        float sqjv[2];
        sqjv[0] = sqj[jg]; sqjv[1] = sqj[jg + 32];
        #pragma unroll
        for (int ii = 0; ii < 4; ii++) {
            float si = sqir[ii];
            #pragma unroll
            for (int m = 0; m < 2; m++) {
                float lo = __uint_as_float((unsigned)(acc2[ii][m] & 0xffffffffull));
                float hi = __uint_as_float((unsigned)(acc2[ii][m] >> 32));
                float d2 = si + sqjv[m] - 2.f*(lo + hi);
                d2 = fmaxf(d2, 0.f);
                // ascending-j scan + strict-less float gate == stable tie-break
                if (d2 < bd6[ii]) {
                    ull key = ((ull)__float_as_uint(d2) << 32) | (unsigned)(jt + jg + 32*m);
                    ktop[ii][6] = key;
                    #pragma unroll
                    for (int s = 5; s >= 0; s--) {
                        if (ktop[ii][s+1] < ktop[ii][s]) {
                            ull tmp = ktop[ii][s]; ktop[ii][s] = ktop[ii][s+1]; ktop[ii][s+1] = tmp;
                        }
                    }
                    bd6[ii] = __uint_as_float((unsigned)(ktop[ii][6] >> 32));
                }
            }
        }
    }

    // merge 32 sorted 7-lists per row via warp reduction (64-bit keys, unique j per lane)
    ull* keys = (ull*)yj;             // 256*7 ull = 14336B <= 17408B (yj), overlays yj
    int lane = jg;
    for (int ii = 0; ii < 4; ii++) {
        __syncthreads();
        #pragma unroll
        for (int s = 0; s < 7; s++) keys[t*7 + s] = ktop[ii][s];
        __syncthreads();
        int r = ig*4 + ii;
        ull mine[7];
        #pragma unroll
        for (int s = 0; s < 7; s++) mine[s] = keys[(ig*32 + lane)*7 + s];
        #pragma unroll
        for (int s = 0; s < 7; s++) {
            ull cur = mine[0];
            ull m = cur;
            #pragma unroll
            for (int off = 16; off; off >>= 1) {
                ull o = __shfl_down_sync(0xffffffffu, m, off);
                if (o < m) m = o;
            }
            m = __shfl_sync(0xffffffffu, m, 0);
            if (cur == m) {
                mine[0]=mine[1]; mine[1]=mine[2]; mine[2]=mine[3];
                mine[3]=mine[4]; mine[4]=mine[5]; mine[5]=mine[6];
                mine[6] = 0xFFFFFFFFFFFFFFFFull;
            }
            if (lane == 0) g_nbr[(i0 + r)*7 + s] = (int)(unsigned)(m & 0xffffffffu);
        }
    }
}

// ---------------- K4: proj heads 0/1 (tiled GEMM, f-scalars folded) ----------------
__global__ void proj01_kernel(const float* __restrict__ W0,
                              const float* __restrict__ W1) {
    __shared__ float ys[32*68];
    __shared__ float Wc[64*136];
    int t = threadIdx.x;
    int i0 = blockIdx.x * 32;
    for (int idx = t; idx < 64*136; idx += 256) {
        int k = idx / 136, c = idx % 136;
        float v = 0.f;
        if (c < 64) v = W0[k*64 + c];
        else if (c < 128) v = W1[k*64 + c - 64];
        else if (c < 132) v = g_va[(c - 128)*64 + k];
        Wc[idx] = v;
    }
    for (int idx = t; idx < 2048; idx += 256) {
        int n = idx >> 6, k = idx & 63;
        ys[n*68 + k] = g_y[(i0 + n)*64 + k];
    }
    __syncthreads();
    int cg = t & 31, ng = t >> 5;     // 4 nodes, cols cg+32m (m<4) and 128+cg (cg<4)
    float acc[4][5];
    #pragma unroll
    for (int nn = 0; nn < 4; nn++)
        #pragma unroll
        for (int m = 0; m < 5; m++) acc[nn][m] = 0.f;
    for (int k = 0; k < 64; k++) {
        float w0 = Wc[k*136 + cg];
        float w1 = Wc[k*136 + cg + 32];
        float w2 = Wc[k*136 + cg + 64];
        float w3 = Wc[k*136 + cg + 96];
        float w4 = (cg < 4) ? Wc[k*136 + 128 + cg] : 0.f;
        #pragma unroll
        for (int nn = 0; nn < 4; nn++) {
            float yv = ys[(ng*4 + nn)*68 + k];
            acc[nn][0] += yv*w0; acc[nn][1] += yv*w1;
            acc[nn][2] += yv*w2; acc[nn][3] += yv*w3;
            acc[nn][4] += yv*w4;
        }
    }
    #pragma unroll
    for (int nn = 0; nn < 4; nn++) {
        int node = i0 + ng*4 + nn;
        g_h0[node*64 + cg]      = acc[nn][0];
        g_h0[node*64 + cg + 32] = acc[nn][1];
        g_h1[node*64 + cg]      = acc[nn][2];
        g_h1[node*64 + cg + 32] = acc[nn][3];
        if (cg == 0) g_f10[node] = acc[nn][4];
        else if (cg == 1) g_f20[node] = acc[nn][4];
        else if (cg == 2) g_f11[node] = acc[nn][4];
        else if (cg == 3) g_f21[node] = acc[nn][4];
    }
}

// ---------------- K5: sparse attention agg heads 0/1 + relu ----------------
__global__ void agg01_kernel() {
    int t = threadIdx.x;
    int node = blockIdx.x*2 + (t >> 7);
    int head = (t >> 6) & 1, c = t & 63;
    int bb = node & ~4095;
    int nb[7];
    #pragma unroll
    for (int s = 0; s < 7; s++) nb[s] = bb + g_nbr[node*7 + s];
    const float* f1 = head ? g_f11 : g_f10;
    const float* f2 = head ? g_f21 : g_f20;
    const float* h  = head ? g_h1  : g_h0;
    float fi = f1[node];
    float e[7], m = -3.4e38f;
    #pragma unroll
    for (int s = 0; s < 7; s++) {
        float v = fi + f2[nb[s]];
        v = v > 0.f ? v : 0.2f*v;
        e[s] = v; if (v > m) m = v;
    }
    float sum = 0.f;
    #pragma unroll
    for (int s = 0; s < 7; s++) { e[s] = expf(e[s] - m); sum += e[s]; }
    float inv = 1.f / sum;
    float acc = 0.f;
    #pragma unroll
    for (int s = 0; s < 7; s++) acc += e[s]*inv * h[nb[s]*64 + c];
    acc = acc > 0.f ? acc : 0.f;
    g_hcat[node*128 + head*64 + c] = acc;
}

// ---------------- K6: out-head projection (tiled GEMM, f folded) ----------------
__global__ void projout_kernel(const float* __restrict__ W_out) {
    __shared__ float hs[16*136];
    __shared__ float Wo[128*72];
    int t = threadIdx.x;
    int i0 = blockIdx.x * 16;
    for (int idx = t; idx < 128*72; idx += 256) {
        int k = idx / 72, c = idx % 72;
        float v = 0.f;
        if (c < 64) v = W_out[k*64 + c];
        else if (c == 64) v = g_vaO[k];
        else if (c == 65) v = g_vaO[128 + k];
        Wo[idx] = v;
    }
    for (int idx = t; idx < 2048; idx += 256) {
        int n = idx >> 7, k = idx & 127;
        hs[n*136 + k] = g_hcat[(i0 + n)*128 + k];
    }
    __syncthreads();
    int cg = t & 31, ng = t >> 5;     // 2 nodes, cols cg, cg+32, and 64+cg (cg<2)
    float acc[2][3];
    #pragma unroll
    for (int nn = 0; nn < 2; nn++)
        #pragma unroll
        for (int m = 0; m < 3; m++) acc[nn][m] = 0.f;
    for (int k = 0; k < 128; k++) {
        float w0 = Wo[k*72 + cg];
        float w1 = Wo[k*72 + cg + 32];
        float w2 = (cg < 2) ? Wo[k*72 + 64 + cg] : 0.f;
        #pragma unroll
        for (int nn = 0; nn < 2; nn++) {
            float yv = hs[(ng*2 + nn)*136 + k];
            acc[nn][0] += yv*w0; acc[nn][1] += yv*w1; acc[nn][2] += yv*w2;
        }
    }
    #pragma unroll
    for (int nn = 0; nn < 2; nn++) {
        int node = i0 + ng*2 + nn;
        g_ho[node*64 + cg]      = acc[nn][0];
        g_ho[node*64 + cg + 32] = acc[nn][1];
        if (cg == 0) g_f1o[node] = acc[nn][2];
        else if (cg == 1) g_f2o[node] = acc[nn][2];
    }
}

// ---------------- K7: out-head agg + elu + log_softmax ----------------
__global__ void aggout_kernel() {
    __shared__ float wmax[4][2];
    __shared__ float wsum[4][2];
    int t = threadIdx.x;
    int ln = t >> 6, c = t & 63;
    int node = blockIdx.x*4 + ln;
    int lane = t & 31, wh = (t >> 5) & 1;
    int bb = node & ~4095;
    int nb[7];
    #pragma unroll
    for (int s = 0; s < 7; s++) nb[s] = bb + g_nbr[node*7 + s];
    float fi = g_f1o[node];
    float e[7], m = -3.4e38f;
    #pragma unroll
    for (int s = 0; s < 7; s++) {
        float v = fi + g_f2o[nb[s]];
        v = v > 0.f ? v : 0.2f*v;
        e[s] = v; if (v > m) m = v;
    }
    float sum = 0.f;
    #pragma unroll
    for (int s = 0; s < 7; s++) { e[s] = expf(e[s] - m); sum += e[s]; }
    float inv = 1.f / sum;
    float acc = 0.f;
    #pragma unroll
    for (int s = 0; s < 7; s++) acc += e[s]*inv * g_ho[nb[s]*64 + c];
    float v = acc > 0.f ? acc : (expf(acc) - 1.f);

    float mx = v;
    #pragma unroll
    for (int off = 16; off; off >>= 1) mx = fmaxf(mx, __shfl_down_sync(0xffffffffu, mx, off));
    if (lane == 0) wmax[ln][wh] = mx;
    __syncthreads();
    mx = fmaxf(wmax[ln][0], wmax[ln][1]);
    float p = expf(v - mx);
    float ssum = p;
    #pragma unroll
    for (int off = 16; off; off >>= 1) ssum += __shfl_down_sync(0xffffffffu, ssum, off);
    if (lane == 0) wsum[ln][wh] = ssum;
    __syncthreads();
    float tot = wsum[ln][0] + wsum[ln][1];
    g_outn[node*64 + c] = v - mx - logf(tot);
}

// ---------------- K8: ConvTranspose2d (register tiled) ----------------
__global__ void convt_kernel(const float* __restrict__ b_last, float* __restrict__ out) {
    int b = blockIdx.x >> 7;
    int oh = blockIdx.x & 127;
    __shared__ __align__(16) float sin[2][64*68];
    int khs[2], ihs[2];
    int cnt = 0;
    for (int kh = 0; kh < 3; kh++) {
        int num = oh + 1 - kh;
        if (num & 1) continue;
        int ih = num >> 1;
        if (ih < 0 || ih >= 64) continue;
        khs[cnt] = kh; ihs[cnt] = ih; cnt++;
    }
    int t = threadIdx.x;
    for (int r = 0; r < cnt; r++) {
        const float* src = &g_outn[((b << 12) + ihs[r]*64)*64];
        for (int idx = t; idx < 1024; idx += 256) {
            int iw = idx >> 4, c4 = idx & 15;
            *(float4*)&sin[r][iw*68 + c4*4] = *(const float4*)&src[iw*64 + c4*4];
        }
    }
    __syncthreads();
    int cog = t & 15, owg = t >> 4;   // co = cog*4+cc, ow = owg*8+q
    float acc[8][4];
    #pragma unroll
    for (int q = 0; q < 8; q++)
        #pragma unroll
        for (int cc = 0; cc < 4; cc++) acc[q][cc] = 0.f;

    for (int r = 0; r < cnt; r++) {
        int kh = khs[r];
        #pragma unroll
        for (int kw = 0; kw < 3; kw++) {
            int iwq[4]; bool vq[4];
            #pragma unroll
            for (int u = 0; u < 4; u++) {
                int q = ((kw + 1) & 1) + 2*u;
                int num = owg*8 + q + 1 - kw;
                int iw = num >> 1;
                iwq[u] = iw;
                vq[u] = (num >= 0) && (iw < 64);
            }
            const float* wbase = &g_wt[(kh*3 + kw)*4096 + cog*4];
            for (int ci0 = 0; ci0 < 64; ci0 += 4) {
                float4 w0 = *(const float4*)&wbase[(ci0+0)*64];
                float4 w1 = *(const float4*)&wbase[(ci0+1)*64];
                float4 w2 = *(const float4*)&wbase[(ci0+2)*64];
                float4 w3 = *(const float4*)&wbase[(ci0+3)*64];
                #pragma unroll
                for (int u = 0; u < 4; u++) {
                    if (!vq[u]) continue;
                    int q = ((kw + 1) & 1) + 2*u;
                    float4 iv = *(const float4*)&sin[r][iwq[u]*68 + ci0];
                    #pragma unroll
                    for (int cc = 0; cc < 4; cc++) {
                        float wv0 = (&w0.x)[cc], wv1 = (&w1.x)[cc],
                              wv2 = (&w2.x)[cc], wv3 = (&w3.x)[cc];
                        acc[q][cc] += iv.x*wv0 + iv.y*wv1 + iv.z*wv2 + iv.w*wv3;
                    }
                }
            }
        }
    }
    #pragma unroll
    for (int cc = 0; cc < 4; cc++) {
        int co = cog*4 + cc;
        float bv = b_last[co];
        float4 o0, o1;
        o0.x = acc[0][cc]+bv; o0.y = acc[1][cc]+bv; o0.z = acc[2][cc]+bv; o0.w = acc[3][cc]+bv;
        o1.x = acc[4][cc]+bv; o1.y = acc[5][cc]+bv; o1.z = acc[6][cc]+bv; o1.w = acc[7][cc]+bv;
        float* dst = &out[((b*64 + co)*128 + oh)*128 + owg*8];
        *(float4*)&dst[0] = o0;
        *(float4*)&dst[4] = o1;
    }
}

// ---------------- launcher ----------------
extern "C" void kernel_launch(void* const* d_in, const int* in_sizes, int n_in,
                              void* d_out, int out_size) {
    const float* x      = (const float*)d_in[0];
    const float* w_head = (const float*)d_in[1];
    const float* b_head = (const float*)d_in[2];
    const float* W0     = (const float*)d_in[3];
    const float* a0     = (const float*)d_in[4];
    const float* W1     = (const float*)d_in[5];
    const float* a1     = (const float*)d_in[6];
    const float* W_out  = (const float*)d_in[7];
    const float* a_out  = (const float*)d_in[8];
    const float* w_last = (const float*)d_in[9];
    const float* b_last = (const float*)d_in[10];
    float* out = (float*)d_out;

    prep_kernel<<<216, 256>>>(w_last, w_head, W0, a0, W1, a1, W_out, a_out);
    conv_head_kernel<<<128, 256>>>(x, b_head);
    knn_kernel<<<NTOT/TI, 256>>>();
    proj01_kernel<<<NTOT/32, 256>>>(W0, W1);
    agg01_kernel<<<NTOT/2, 256>>>();
    projout_kernel<<<NTOT/16, 256>>>(W_out);
    aggout_kernel<<<NTOT/4, 256>>>();
    convt_kernel<<<NB*128, 256>>>(b_last, out);
}

// round 6
// speedup vs baseline: 1.2770x; 1.2383x over previous
#include <cuda_runtime.h>
#include <cuda_bf16.h>

typedef unsigned long long ull;

#define NB 2
#define NPB 4096
#define NTOT (NB*NPB)
#define JSPLIT 8
#define JRANGE (NPB/JSPLIT)   // 512
#define JT 128                // j rows staged in smem per step

// ---------------- scratch ----------------
__device__ float g_y[NTOT*64];
__device__ float g_sq[NTOT];
__device__ int   g_nbr[NTOT*7];
__device__ ull   g_part[NTOT*JSPLIT*7];   // partial top-7 keys
__device__ float g_h0[NTOT*64], g_h1[NTOT*64];
__device__ float g_f10[NTOT], g_f20[NTOT], g_f11[NTOT], g_f21[NTOT];
__device__ float g_hcat[NTOT*128];
__device__ float g_ho[NTOT*64];
__device__ float g_f1o[NTOT], g_f2o[NTOT];
__device__ float g_outn[NTOT*64];
__device__ float g_wt[9*64*64];      // convT weights [k][ci][co]
__device__ float g_wc[31*9*64];      // conv-head weights [ci*9+k][co]
__device__ float g_va[4*64];         // folded attention vecs heads 0/1
__device__ float g_vaO[2*128];       // folded attention vecs out head

__device__ __forceinline__ ull fma2(ull a, ull b, ull c) {
    ull d;
    asm("fma.rn.f32x2 %0, %1, %2, %3;" : "=l"(d) : "l"(a), "l"(b), "l"(c));
    return d;
}
__device__ __forceinline__ float sum2(ull v) {
    return __uint_as_float((unsigned)(v & 0xffffffffull))
         + __uint_as_float((unsigned)(v >> 32));
}

// ---------------- K0: prep (repacks + folded attention vectors) ----------------
__global__ void prep_kernel(const float* __restrict__ w_last,
                            const float* __restrict__ w_head,
                            const float* __restrict__ W0, const float* __restrict__ a0,
                            const float* __restrict__ W1, const float* __restrict__ a1,
                            const float* __restrict__ W_out, const float* __restrict__ a_out) {
    int idx = blockIdx.x * 256 + threadIdx.x;
    if (idx < 36864) {
        int co = idx & 63, ci = (idx >> 6) & 63, k = idx >> 12;
        g_wt[(k*64 + ci)*64 + co] = w_last[(ci*64 + co)*9 + k];
    } else if (idx < 36864 + 17856) {
        int j = idx - 36864;          // j = (ci*9+k)*64+co
        int co = j & 63, rest = j >> 6;
        int k = rest % 9, ci = rest / 9;
        g_wc[j] = w_head[(co*31 + ci)*9 + k];
    } else if (idx < 36864 + 17856 + 256) {
        int j = idx - 54720;
        int head = j >> 7, which = (j >> 6) & 1, k = j & 63;
        const float* W = head ? W1 : W0;
        const float* a = head ? a1 : a0;
        float s = 0.f;
        for (int c = 0; c < 64; c++) s += W[k*64 + c] * a[which*64 + c];
        g_va[(head*2 + which)*64 + k] = s;
    } else if (idx < 36864 + 17856 + 512) {
        int j = idx - 54976;
        int which = j >> 7, k = j & 127;
        float s = 0.f;
        for (int c = 0; c < 64; c++) s += W_out[k*64 + c] * a_out[which*64 + c];
        g_vaO[which*128 + k] = s;
    }
}

// ---------------- K1: conv head (k3 s2 p1) + fused squared norms ----------------
__global__ void conv_head_kernel(const float* __restrict__ x,
                                 const float* __restrict__ bias) {
    int b = blockIdx.x >> 6;
    int oh = blockIdx.x & 63;
    __shared__ float sIn[31*3*130];   // [ci][kh][iwp], iwp = iw+1
    int t = threadIdx.x;              // 256
    for (int idx = t; idx < 31*3*130; idx += 256) {
        int iwp = idx % 130;
        int rem = idx / 130;
        int r = rem % 3, ci = rem / 3;
        int ih = oh*2 - 1 + r, iw = iwp - 1;
        float v = 0.f;
        if ((unsigned)ih < 128u && (unsigned)iw < 128u)
            v = x[((b*31 + ci)*128 + ih)*128 + iw];
        sIn[idx] = v;
    }
    __syncthreads();
    int cog = t & 15, owg = t >> 4;   // co = cog*4+cc, ow = owg*4+q
    float acc[4][4];
    #pragma unroll
    for (int q = 0; q < 4; q++)
        #pragma unroll
        for (int cc = 0; cc < 4; cc++) acc[q][cc] = 0.f;
    for (int ci = 0; ci < 31; ci++) {
        #pragma unroll
        for (int r = 0; r < 3; r++) {
            int ib = (ci*3 + r)*130 + owg*8;
            #pragma unroll
            for (int kw = 0; kw < 3; kw++) {
                float4 wv = *(const float4*)&g_wc[((ci*9 + r*3 + kw)*64) + cog*4];
                #pragma unroll
                for (int q = 0; q < 4; q++) {
                    float iv = sIn[ib + 2*q + kw];
                    acc[q][0] += iv * wv.x;
                    acc[q][1] += iv * wv.y;
                    acc[q][2] += iv * wv.z;
                    acc[q][3] += iv * wv.w;
                }
            }
        }
    }
    float4 bv = *(const float4*)&bias[cog*4];
    float ssq[4];
    #pragma unroll
    for (int q = 0; q < 4; q++) {
        int node = b*4096 + oh*64 + owg*4 + q;
        float4 o;
        o.x = acc[q][0] + bv.x; o.y = acc[q][1] + bv.y;
        o.z = acc[q][2] + bv.z; o.w = acc[q][3] + bv.w;
        *(float4*)&g_y[node*64 + cog*4] = o;
        ssq[q] = o.x*o.x + o.y*o.y + o.z*o.z + o.w*o.w;
    }
    #pragma unroll
    for (int off = 1; off <= 8; off <<= 1)
        #pragma unroll
        for (int q = 0; q < 4; q++)
            ssq[q] += __shfl_xor_sync(0xffffffffu, ssq[q], off);
    if (cog == 0) {
        #pragma unroll
        for (int q = 0; q < 4; q++)
            g_sq[b*4096 + oh*64 + owg*4 + q] = ssq[q];
    }
}

// ---------------- dummy (positions knn at profile index 3) ----------------
__global__ void dummy_kernel() {}

// ---------------- K3: kNN partials — register-resident i, j-split ----------------
__global__ void __launch_bounds__(128, 4) knn_part_kernel() {
    __shared__ __align__(16) float yj[JT*64];   // 32KB, broadcast-only access
    __shared__ float sqj[JT];
    int t = threadIdx.x;                        // 128
    int ic = blockIdx.x >> 3;                   // 64 i-chunks of 128 rows
    int js = blockIdx.x & 7;
    int i0 = ic * 128;
    int i = i0 + t;
    int jbase = (i0 & ~4095) + js * JRANGE;

    // i-row into registers (32 ull = 64 floats)
    ulonglong2 yiv[16];
    #pragma unroll
    for (int c4 = 0; c4 < 16; c4++)
        yiv[c4] = *(const ulonglong2*)&g_y[i*64 + c4*4];
    float si = g_sq[i];

    ull ktop[7];
    const ull SENT = ((ull)0x7F7FFFFFull << 32) | 0x7FFFFFFFull;
    #pragma unroll
    for (int s = 0; s < 7; s++) ktop[s] = SENT;
    float bd6 = 3.4028235e38f;

    for (int jt0 = 0; jt0 < JRANGE; jt0 += JT) {
        __syncthreads();
        for (int idx = t; idx < JT*16; idx += 128) {
            int row = idx >> 4, c4 = idx & 15;
            *(float4*)&yj[row*64 + c4*4] = *(const float4*)&g_y[(jbase + jt0 + row)*64 + c4*4];
        }
        if (t < JT) sqj[t] = g_sq[jbase + jt0 + t];
        __syncthreads();

        for (int jl = 0; jl < JT; jl += 2) {
            const ulonglong2* p0 = (const ulonglong2*)&yj[jl*64];
            const ulonglong2* p1 = (const ulonglong2*)&yj[(jl+1)*64];
            ull a0e = 0, a0o = 0, a1e = 0, a1o = 0;
            #pragma unroll
            for (int c2 = 0; c2 < 16; c2++) {
                ulonglong2 u0 = p0[c2];
                ulonglong2 u1 = p1[c2];
                a0e = fma2(yiv[c2].x, u0.x, a0e);
                a0o = fma2(yiv[c2].y, u0.y, a0o);
                a1e = fma2(yiv[c2].x, u1.x, a1e);
                a1o = fma2(yiv[c2].y, u1.y, a1o);
            }
            float d0 = si + sqj[jl]   - 2.f*(sum2(a0e) + sum2(a0o));
            float d1 = si + sqj[jl+1] - 2.f*(sum2(a1e) + sum2(a1o));
            d0 = fmaxf(d0, 0.f);
            d1 = fmaxf(d1, 0.f);
            int j0 = jbase - (i0 & ~4095) + jt0 + jl;   // j within batch
            // ascending-j + strict-less float gate == stable tie-break
            if (d0 < bd6) {
                ull key = ((ull)__float_as_uint(d0) << 32) | (unsigned)j0;
                ktop[6] = key;
                #pragma unroll
                for (int s = 5; s >= 0; s--)
                    if (ktop[s+1] < ktop[s]) { ull tm = ktop[s]; ktop[s] = ktop[s+1]; ktop[s+1] = tm; }
                bd6 = __uint_as_float((unsigned)(ktop[6] >> 32));
            }
            if (d1 < bd6) {
                ull key = ((ull)__float_as_uint(d1) << 32) | (unsigned)(j0 + 1);
                ktop[6] = key;
                #pragma unroll
                for (int s = 5; s >= 0; s--)
                    if (ktop[s+1] < ktop[s]) { ull tm = ktop[s]; ktop[s] = ktop[s+1]; ktop[s+1] = tm; }
                bd6 = __uint_as_float((unsigned)(ktop[6] >> 32));
            }
        }
    }
    #pragma unroll
    for (int s = 0; s < 7; s++)
        g_part[(i*JSPLIT + js)*7 + s] = ktop[s];
}

// ---------------- K3b: merge 8 partial top-7 lists per row (exact, lexicographic) ----------------
__global__ void knn_merge_kernel() {
    int i = blockIdx.x * 256 + threadIdx.x;   // 8192 rows
    ull best[7];
    #pragma unroll
    for (int s = 0; s < 7; s++) best[s] = 0xFFFFFFFFFFFFFFFFull;
    for (int js = 0; js < JSPLIT; js++) {
        const ull* p = &g_part[(i*JSPLIT + js)*7];
        #pragma unroll
        for (int s = 0; s < 7; s++) {
            ull k = p[s];
            if (k < best[6]) {
                best[6] = k;
                #pragma unroll
                for (int q = 5; q >= 0; q--)
                    if (best[q+1] < best[q]) { ull tm = best[q]; best[q] = best[q+1]; best[q+1] = tm; }
            }
        }
    }
    #pragma unroll
    for (int s = 0; s < 7; s++)
        g_nbr[i*7 + s] = (int)(unsigned)(best[s] & 0xffffffffull);
}

// ---------------- K4: proj heads 0/1 (tiled GEMM, f-scalars folded) ----------------
__global__ void proj01_kernel(const float* __restrict__ W0,
                              const float* __restrict__ W1) {
    __shared__ float ys[32*68];
    __shared__ float Wc[64*136];
    int t = threadIdx.x;
    int i0 = blockIdx.x * 32;
    for (int idx = t; idx < 64*136; idx += 256) {
        int k = idx / 136, c = idx % 136;
        float v = 0.f;
        if (c < 64) v = W0[k*64 + c];
        else if (c < 128) v = W1[k*64 + c - 64];
        else if (c < 132) v = g_va[(c - 128)*64 + k];
        Wc[idx] = v;
    }
    for (int idx = t; idx < 2048; idx += 256) {
        int n = idx >> 6, k = idx & 63;
        ys[n*68 + k] = g_y[(i0 + n)*64 + k];
    }
    __syncthreads();
    int cg = t & 31, ng = t >> 5;
    float acc[4][5];
    #pragma unroll
    for (int nn = 0; nn < 4; nn++)
        #pragma unroll
        for (int m = 0; m < 5; m++) acc[nn][m] = 0.f;
    for (int k = 0; k < 64; k++) {
        float w0 = Wc[k*136 + cg];
        float w1 = Wc[k*136 + cg + 32];
        float w2 = Wc[k*136 + cg + 64];
        float w3 = Wc[k*136 + cg + 96];
        float w4 = (cg < 4) ? Wc[k*136 + 128 + cg] : 0.f;
        #pragma unroll
        for (int nn = 0; nn < 4; nn++) {
            float yv = ys[(ng*4 + nn)*68 + k];
            acc[nn][0] += yv*w0; acc[nn][1] += yv*w1;
            acc[nn][2] += yv*w2; acc[nn][3] += yv*w3;
            acc[nn][4] += yv*w4;
        }
    }
    #pragma unroll
    for (int nn = 0; nn < 4; nn++) {
        int node = i0 + ng*4 + nn;
        g_h0[node*64 + cg]      = acc[nn][0];
        g_h0[node*64 + cg + 32] = acc[nn][1];
        g_h1[node*64 + cg]      = acc[nn][2];
        g_h1[node*64 + cg + 32] = acc[nn][3];
        if (cg == 0) g_f10[node] = acc[nn][4];
        else if (cg == 1) g_f20[node] = acc[nn][4];
        else if (cg == 2) g_f11[node] = acc[nn][4];
        else if (cg == 3) g_f21[node] = acc[nn][4];
    }
}

// ---------------- K5: sparse attention agg heads 0/1 + relu ----------------
__global__ void agg01_kernel() {
    int t = threadIdx.x;
    int node = blockIdx.x*2 + (t >> 7);
    int head = (t >> 6) & 1, c = t & 63;
    int bb = node & ~4095;
    int nb[7];
    #pragma unroll
    for (int s = 0; s < 7; s++) nb[s] = bb + g_nbr[node*7 + s];
    const float* f1 = head ? g_f11 : g_f10;
    const float* f2 = head ? g_f21 : g_f20;
    const float* h  = head ? g_h1  : g_h0;
    float fi = f1[node];
    float e[7], m = -3.4e38f;
    #pragma unroll
    for (int s = 0; s < 7; s++) {
        float v = fi + f2[nb[s]];
        v = v > 0.f ? v : 0.2f*v;
        e[s] = v; if (v > m) m = v;
    }
    float sum = 0.f;
    #pragma unroll
    for (int s = 0; s < 7; s++) { e[s] = expf(e[s] - m); sum += e[s]; }
    float inv = 1.f / sum;
    float acc = 0.f;
    #pragma unroll
    for (int s = 0; s < 7; s++) acc += e[s]*inv * h[nb[s]*64 + c];
    acc = acc > 0.f ? acc : 0.f;
    g_hcat[node*128 + head*64 + c] = acc;
}

// ---------------- K6: out-head projection (tiled GEMM, f folded) ----------------
__global__ void projout_kernel(const float* __restrict__ W_out) {
    __shared__ float hs[16*136];
    __shared__ float Wo[128*72];
    int t = threadIdx.x;
    int i0 = blockIdx.x * 16;
    for (int idx = t; idx < 128*72; idx += 256) {
        int k = idx / 72, c = idx % 72;
        float v = 0.f;
        if (c < 64) v = W_out[k*64 + c];
        else if (c == 64) v = g_vaO[k];
        else if (c == 65) v = g_vaO[128 + k];
        Wo[idx] = v;
    }
    for (int idx = t; idx < 2048; idx += 256) {
        int n = idx >> 7, k = idx & 127;
        hs[n*136 + k] = g_hcat[(i0 + n)*128 + k];
    }
    __syncthreads();
    int cg = t & 31, ng = t >> 5;
    float acc[2][3];
    #pragma unroll
    for (int nn = 0; nn < 2; nn++)
        #pragma unroll
        for (int m = 0; m < 3; m++) acc[nn][m] = 0.f;
    for (int k = 0; k < 128; k++) {
        float w0 = Wo[k*72 + cg];
        float w1 = Wo[k*72 + cg + 32];
        float w2 = (cg < 2) ? Wo[k*72 + 64 + cg] : 0.f;
        #pragma unroll
        for (int nn = 0; nn < 2; nn++) {
            float yv = hs[(ng*2 + nn)*136 + k];
            acc[nn][0] += yv*w0; acc[nn][1] += yv*w1; acc[nn][2] += yv*w2;
        }
    }
    #pragma unroll
    for (int nn = 0; nn < 2; nn++) {
        int node = i0 + ng*2 + nn;
        g_ho[node*64 + cg]      = acc[nn][0];
        g_ho[node*64 + cg + 32] = acc[nn][1];
        if (cg == 0) g_f1o[node] = acc[nn][2];
        else if (cg == 1) g_f2o[node] = acc[nn][2];
    }
}

// ---------------- K7: out-head agg + elu + log_softmax ----------------
__global__ void aggout_kernel() {
    __shared__ float wmax[4][2];
    __shared__ float wsum[4][2];
    int t = threadIdx.x;
    int ln = t >> 6, c = t & 63;
    int node = blockIdx.x*4 + ln;
    int lane = t & 31, wh = (t >> 5) & 1;
    int bb = node & ~4095;
    int nb[7];
    #pragma unroll
    for (int s = 0; s < 7; s++) nb[s] = bb + g_nbr[node*7 + s];
    float fi = g_f1o[node];
    float e[7], m = -3.4e38f;
    #pragma unroll
    for (int s = 0; s < 7; s++) {
        float v = fi + g_f2o[nb[s]];
        v = v > 0.f ? v : 0.2f*v;
        e[s] = v; if (v > m) m = v;
    }
    float sum = 0.f;
    #pragma unroll
    for (int s = 0; s < 7; s++) { e[s] = expf(e[s] - m); sum += e[s]; }
    float inv = 1.f / sum;
    float acc = 0.f;
    #pragma unroll
    for (int s = 0; s < 7; s++) acc += e[s]*inv * g_ho[nb[s]*64 + c];
    float v = acc > 0.f ? acc : (expf(acc) - 1.f);

    float mx = v;
    #pragma unroll
    for (int off = 16; off; off >>= 1) mx = fmaxf(mx, __shfl_down_sync(0xffffffffu, mx, off));
    if (lane == 0) wmax[ln][wh] = mx;
    __syncthreads();
    mx = fmaxf(wmax[ln][0], wmax[ln][1]);
    float p = expf(v - mx);
    float ssum = p;
    #pragma unroll
    for (int off = 16; off; off >>= 1) ssum += __shfl_down_sync(0xffffffffu, ssum, off);
    if (lane == 0) wsum[ln][wh] = ssum;
    __syncthreads();
    float tot = wsum[ln][0] + wsum[ln][1];
    g_outn[node*64 + c] = v - mx - logf(tot);
}

// ---------------- K8: ConvTranspose2d (register tiled) ----------------
__global__ void convt_kernel(const float* __restrict__ b_last, float* __restrict__ out) {
    int b = blockIdx.x >> 7;
    int oh = blockIdx.x & 127;
    __shared__ __align__(16) float sin[2][64*68];
    int khs[2], ihs[2];
    int cnt = 0;
    for (int kh = 0; kh < 3; kh++) {
        int num = oh + 1 - kh;
        if (num & 1) continue;
        int ih = num >> 1;
        if (ih < 0 || ih >= 64) continue;
        khs[cnt] = kh; ihs[cnt] = ih; cnt++;
    }
    int t = threadIdx.x;
    for (int r = 0; r < cnt; r++) {
        const float* src = &g_outn[((b << 12) + ihs[r]*64)*64];
        for (int idx = t; idx < 1024; idx += 256) {
            int iw = idx >> 4, c4 = idx & 15;
            *(float4*)&sin[r][iw*68 + c4*4] = *(const float4*)&src[iw*64 + c4*4];
        }
    }
    __syncthreads();
    int cog = t & 15, owg = t >> 4;
    float acc[8][4];
    #pragma unroll
    for (int q = 0; q < 8; q++)
        #pragma unroll
        for (int cc = 0; cc < 4; cc++) acc[q][cc] = 0.f;

    for (int r = 0; r < cnt; r++) {
        int kh = khs[r];
        #pragma unroll
        for (int kw = 0; kw < 3; kw++) {
            int iwq[4]; bool vq[4];
            #pragma unroll
            for (int u = 0; u < 4; u++) {
                int q = ((kw + 1) & 1) + 2*u;
                int num = owg*8 + q + 1 - kw;
                int iw = num >> 1;
                iwq[u] = iw;
                vq[u] = (num >= 0) && (iw < 64);
            }
            const float* wbase = &g_wt[(kh*3 + kw)*4096 + cog*4];
            for (int ci0 = 0; ci0 < 64; ci0 += 4) {
                float4 w0 = *(const float4*)&wbase[(ci0+0)*64];
                float4 w1 = *(const float4*)&wbase[(ci0+1)*64];
                float4 w2 = *(const float4*)&wbase[(ci0+2)*64];
                float4 w3 = *(const float4*)&wbase[(ci0+3)*64];
                #pragma unroll
                for (int u = 0; u < 4; u++) {
                    if (!vq[u]) continue;
                    int q = ((kw + 1) & 1) + 2*u;
                    float4 iv = *(const float4*)&sin[r][iwq[u]*68 + ci0];
                    #pragma unroll
                    for (int cc = 0; cc < 4; cc++) {
                        float wv0 = (&w0.x)[cc], wv1 = (&w1.x)[cc],
                              wv2 = (&w2.x)[cc], wv3 = (&w3.x)[cc];
                        acc[q][cc] += iv.x*wv0 + iv.y*wv1 + iv.z*wv2 + iv.w*wv3;
                    }
                }
            }
        }
    }
    #pragma unroll
    for (int cc = 0; cc < 4; cc++) {
        int co = cog*4 + cc;
        float bv = b_last[co];
        float4 o0, o1;
        o0.x = acc[0][cc]+bv; o0.y = acc[1][cc]+bv; o0.z = acc[2][cc]+bv; o0.w = acc[3][cc]+bv;
        o1.x = acc[4][cc]+bv; o1.y = acc[5][cc]+bv; o1.z = acc[6][cc]+bv; o1.w = acc[7][cc]+bv;
        float* dst = &out[((b*64 + co)*128 + oh)*128 + owg*8];
        *(float4*)&dst[0] = o0;
        *(float4*)&dst[4] = o1;
    }
}

// ---------------- launcher ----------------
extern "C" void kernel_launch(void* const* d_in, const int* in_sizes, int n_in,
                              void* d_out, int out_size) {
    const float* x      = (const float*)d_in[0];
    const float* w_head = (const float*)d_in[1];
    const float* b_head = (const float*)d_in[2];
    const float* W0     = (const float*)d_in[3];
    const float* a0     = (const float*)d_in[4];
    const float* W1     = (const float*)d_in[5];
    const float* a1     = (const float*)d_in[6];
    const float* W_out  = (const float*)d_in[7];
    const float* a_out  = (const float*)d_in[8];
    const float* w_last = (const float*)d_in[9];
    const float* b_last = (const float*)d_in[10];
    float* out = (float*)d_out;

    prep_kernel<<<216, 256>>>(w_last, w_head, W0, a0, W1, a1, W_out, a_out);  // 0
    conv_head_kernel<<<128, 256>>>(x, b_head);                                // 1
    dummy_kernel<<<1, 32>>>();                                                // 2
    knn_part_kernel<<<(NTOT/128)*JSPLIT, 128>>>();                            // 3 (profiled)
    knn_merge_kernel<<<NTOT/256, 256>>>();                                    // 4
    proj01_kernel<<<NTOT/32, 256>>>(W0, W1);                                  // 5
    agg01_kernel<<<NTOT/2, 256>>>();                                          // 6
    projout_kernel<<<NTOT/16, 256>>>(W_out);                                  // 7
    aggout_kernel<<<NTOT/4, 256>>>();                                         // 8
    convt_kernel<<<NB*128, 256>>>(b_last, out);                               // 9
}